// round 14
// baseline (speedup 1.0000x reference)
#include <cuda_runtime.h>
#include <math.h>

#define DT 0.1f
#define EPS_STAT 0.01f

// slot-per-thread fused kernel with full measurement prefetch:
//   thread f owns one float4 slot of the 5-float4-per-4-elements row pattern.
//   It prefetches ALL 10 measurement rows of its batch element as independent
//   loads (no dependent chain), runs the 9-step est recursion purely in
//   registers, then emits all 39 rows as one unrolled burst of independent
//   coalesced STG.128. No scratch, no staging smem, no sync in the hot path.
// Row pattern: cb0:(p0x,p0y,s,s) cb1:(0,p1x,p1y,s) cb2:(s,0,p2x,p2y)
//              cb3:(s,s,0,p3x)   cb4:(p3y,s,s,0)
template <int BLOCK, int NEST, int NPRED>
__global__ void __launch_bounds__(BLOCK)
kalman_fused(const float* __restrict__ in, float* __restrict__ out,
             const float* __restrict__ sa_p, const float* __restrict__ so_p,
             const float* __restrict__ si_p, int B) {
    __shared__ float4 gt[NEST];   // (K0, K1, s, 0)
    __shared__ float  st[NPRED];  // s per pred row

    const int tid = threadIdx.x;

    if (tid == 0) {
        const float sa = *sa_p, so = *so_p, si = *si_p;
        const float g0  = DT * DT * 0.5f;
        const float q00 = sa * sa * (g0 * g0);
        const float q01 = sa * sa * (g0 * DT);
        const float q11 = sa * sa * (DT * DT);
        const float r   = so * so;
        const float eps2 = EPS_STAT * EPS_STAT;
        float P00 = si * si, P01 = 0.0f, P11 = si * si;
        #pragma unroll
        for (int k = 0; k < NEST; k++) {
            float a = P00 + 2.0f * DT * P01 + DT * DT * P11 + q00;
            float c = P01 + DT * P11 + q01;
            float d = P11 + q11;
            P00 = a; P01 = c; P11 = d;
            float S = P00 + r, rs = 1.0f / S;
            float K0 = P00 * rs, K1 = P01 * rs;
            float omk = 1.0f - K0;
            float A00 = omk * P00;
            float A01 = omk * P01;
            float A10 = P01 - K1 * P00;
            float A11 = P11 - K1 * P01;
            P00 =  A00 * omk      + r * K0 * K0;
            P01 = -A00 * K1 + A01 + r * K0 * K1;
            P11 = -A10 * K1 + A11 + r * K1 * K1;
            gt[k] = make_float4(K0, K1, sqrtf(fmaxf(P00, eps2)), 0.0f);
        }
        #pragma unroll
        for (int j = 0; j < NPRED; j++) {
            float a = P00 + 2.0f * DT * P01 + DT * DT * P11 + q00;
            float c = P01 + DT * P11 + q01;
            float d = P11 + q11;
            P00 = a; P01 = c; P11 = d;
            st[j] = sqrtf(fmaxf(P00, eps2));
        }
    }
    __syncthreads();

    const int f  = blockIdx.x * BLOCK + tid;
    const int G4 = (B * 5) >> 2;
    if (f >= G4) return;

    const int cb = f % 5;
    const int e  = 4 * (f / 5) + ((cb < 3) ? cb : 3);

    float4 pxm, pym, sm;
    switch (cb) {
        case 0: pxm = make_float4(1,0,0,0); pym = make_float4(0,1,0,0); sm = make_float4(0,0,1,1); break;
        case 1: pxm = make_float4(0,1,0,0); pym = make_float4(0,0,1,0); sm = make_float4(0,0,0,1); break;
        case 2: pxm = make_float4(0,0,1,0); pym = make_float4(0,0,0,1); sm = make_float4(1,0,0,0); break;
        case 3: pxm = make_float4(0,0,0,1); pym = make_float4(0,0,0,0); sm = make_float4(1,1,0,0); break;
        default:pxm = make_float4(0,0,0,0); pym = make_float4(1,0,0,0); sm = make_float4(0,1,1,0); break;
    }

    // ---- prefetch ALL measurement rows: independent loads, MLP = NEST+1 ----
    const float2* __restrict__ zin = reinterpret_cast<const float2*>(in);
    float2 zr[NEST + 1];
    #pragma unroll
    for (int t = 0; t <= NEST; t++) zr[t] = zin[(size_t)t * B + e];

    // ---- register-only est recursion ----
    float px = zr[0].x, py = zr[0].y;
    float vx = (zr[1].x - zr[0].x) * (1.0f / DT);
    float vy = (zr[1].y - zr[0].y) * (1.0f / DT);

    float rpx[NEST], rpy[NEST];
    #pragma unroll
    for (int t = 0; t < NEST; t++) {
        px += DT * vx;
        py += DT * vy;
        float4 g = gt[t];
        float yx = zr[t + 1].x - px, yy = zr[t + 1].y - py;
        px += g.x * yx; vx += g.y * yx;
        py += g.x * yy; vy += g.y * yy;
        rpx[t] = px; rpy[t] = py;
    }

    // ---- one unrolled burst of 39 independent coalesced STG.128 ----
    float4* __restrict__ out4 = reinterpret_cast<float4*>(out) + f;
    const long long stride = G4;

    #pragma unroll
    for (int t = 0; t < NEST; t++) {
        const float s = gt[t].z;
        float4 v;
        v.x = fmaf(rpx[t], pxm.x, fmaf(rpy[t], pym.x, s * sm.x));
        v.y = fmaf(rpx[t], pxm.y, fmaf(rpy[t], pym.y, s * sm.y));
        v.z = fmaf(rpx[t], pxm.z, fmaf(rpy[t], pym.z, s * sm.z));
        v.w = fmaf(rpx[t], pxm.w, fmaf(rpy[t], pym.w, s * sm.w));
        out4[(long long)t * stride] = v;
    }

    float qx = px, qy = py;
    const float dx = DT * vx, dy = DT * vy;
    #pragma unroll
    for (int j = 0; j < NPRED; j++) {
        qx += dx; qy += dy;
        const float s = st[j];
        float4 v;
        v.x = fmaf(qx, pxm.x, fmaf(qy, pym.x, s * sm.x));
        v.y = fmaf(qx, pxm.y, fmaf(qy, pym.y, s * sm.y));
        v.z = fmaf(qx, pxm.z, fmaf(qy, pym.z, s * sm.z));
        v.w = fmaf(qx, pxm.w, fmaf(qy, pym.w, s * sm.w));
        out4[(long long)(NEST + j) * stride] = v;
    }
}

// generic fallback for unexpected shapes
__global__ void kalman_generic(const float* __restrict__ in, float* __restrict__ out,
                               const float* __restrict__ sa_p, const float* __restrict__ so_p,
                               const float* __restrict__ si_p,
                               int B, int n_est, int n_pred) {
    const int b = blockIdx.x * blockDim.x + threadIdx.x;
    if (b >= B) return;
    const float sa = *sa_p, so = *so_p, si = *si_p;
    const float g0  = DT * DT * 0.5f;
    const float q00 = sa * sa * (g0 * g0);
    const float q01 = sa * sa * (g0 * DT);
    const float q11 = sa * sa * (DT * DT);
    const float r   = so * so;
    const float eps2 = EPS_STAT * EPS_STAT;
    float P00 = si * si, P01 = 0.0f, P11 = si * si;
    const float2* zin = reinterpret_cast<const float2*>(in);
    float2 z0 = zin[b], z1 = zin[(size_t)B + b];
    float px = z0.x, py = z0.y;
    float vx = (z1.x - z0.x) / DT, vy = (z1.y - z0.y) / DT;
    for (int t = 0; t < n_est + n_pred; t++) {
        float a = P00 + 2.0f * DT * P01 + DT * DT * P11 + q00;
        float c = P01 + DT * P11 + q01;
        float d = P11 + q11;
        P00 = a; P01 = c; P11 = d;
        px += DT * vx; py += DT * vy;
        if (t < n_est) {
            float2 z = zin[(size_t)(t + 1) * B + b];
            float S = P00 + r, rs = 1.0f / S;
            float K0 = P00 * rs, K1 = P01 * rs;
            float yx = z.x - px, yy = z.y - py;
            px += K0 * yx; vx += K1 * yx;
            py += K0 * yy; vy += K1 * yy;
            float omk = 1.0f - K0;
            float A00 = omk * P00, A01 = omk * P01;
            float A10 = P01 - K1 * P00, A11 = P11 - K1 * P01;
            P00 =  A00 * omk      + r * K0 * K0;
            P01 = -A00 * K1 + A01 + r * K0 * K1;
            P11 = -A10 * K1 + A11 + r * K1 * K1;
        }
        float s = sqrtf(fmaxf(P00, eps2));
        float* dptr = out + (long long)t * B * 5 + (long long)b * 5;
        dptr[0] = px; dptr[1] = py; dptr[2] = s; dptr[3] = s; dptr[4] = 0.0f;
    }
}

extern "C" void kernel_launch(void* const* d_in, const int* in_sizes, int n_in,
                              void* d_out, int out_size) {
    const float* inputs  = (const float*)d_in[0];
    const float* sigma_a = (const float*)d_in[1];
    const float* sigma_o = (const float*)d_in[2];
    const float* sigma_i = (const float*)d_in[3];

    const int T_OBS = 10;
    const int B = in_sizes[0] / (T_OBS * 2);
    const int n_est = T_OBS - 1;                // 9
    const int totalSteps = out_size / (B * 5);  // 39
    const int n_pred = totalSteps - n_est;      // 30

    if (n_est == 9 && n_pred == 30 && (B % 4) == 0) {
        constexpr int BLOCK = 128;
        const int G4 = (B * 5) / 4;
        const int grid = (G4 + BLOCK - 1) / BLOCK;
        kalman_fused<BLOCK, 9, 30><<<grid, BLOCK>>>(
            inputs, (float*)d_out, sigma_a, sigma_o, sigma_i, B);
    } else {
        const int grid = (B + 255) / 256;
        kalman_generic<<<grid, 256>>>(inputs, (float*)d_out,
                                      sigma_a, sigma_o, sigma_i,
                                      B, n_est, n_pred);
    }
}

// round 15
// speedup vs baseline: 1.1029x; 1.1029x over previous
#include <cuda_runtime.h>
#include <math.h>

#define DT 0.1f
#define EPS_STAT 0.01f

// slot-per-thread fused kernel:
//   thread f owns one float4 slot of the 5-float4-per-4-elements row pattern,
//   prefetches all 10 measurement rows of its element (independent loads),
//   runs the 9-step est recursion in registers, then emits all 39 rows as
//   independent coalesced streaming STG.128. Pred rows are assembled
//   incrementally (v += cvec + ds*sm), 8 ops/row instead of 12.
// Row pattern: cb0:(p0x,p0y,s,s) cb1:(0,p1x,p1y,s) cb2:(s,0,p2x,p2y)
//              cb3:(s,s,0,p3x)   cb4:(p3y,s,s,0)
template <int BLOCK, int NEST, int NPRED>
__global__ void __launch_bounds__(BLOCK)
kalman_fused(const float* __restrict__ in, float* __restrict__ out,
             const float* __restrict__ sa_p, const float* __restrict__ so_p,
             const float* __restrict__ si_p, int B) {
    __shared__ float4 gt[NEST];       // (K0, K1, s, 0) per est step
    __shared__ float  st[NPRED];      // s per pred row
    __shared__ float  dst_[NPRED];    // ds per pred row (st[j]-st[j-1]; dst_[0] = st[0]-s_est_last)

    const int tid = threadIdx.x;

    if (tid == 0) {
        const float sa = *sa_p, so = *so_p, si = *si_p;
        const float g0  = DT * DT * 0.5f;
        const float q00 = sa * sa * (g0 * g0);
        const float q01 = sa * sa * (g0 * DT);
        const float q11 = sa * sa * (DT * DT);
        const float r   = so * so;
        const float eps2 = EPS_STAT * EPS_STAT;
        float P00 = si * si, P01 = 0.0f, P11 = si * si;
        float sprev = 0.0f;
        #pragma unroll
        for (int k = 0; k < NEST; k++) {
            float a = P00 + 2.0f * DT * P01 + DT * DT * P11 + q00;
            float c = P01 + DT * P11 + q01;
            float d = P11 + q11;
            P00 = a; P01 = c; P11 = d;
            float S = P00 + r, rs = 1.0f / S;
            float K0 = P00 * rs, K1 = P01 * rs;
            float omk = 1.0f - K0;
            float A00 = omk * P00;
            float A01 = omk * P01;
            float A10 = P01 - K1 * P00;
            float A11 = P11 - K1 * P01;
            P00 =  A00 * omk      + r * K0 * K0;
            P01 = -A00 * K1 + A01 + r * K0 * K1;
            P11 = -A10 * K1 + A11 + r * K1 * K1;
            sprev = sqrtf(fmaxf(P00, eps2));
            gt[k] = make_float4(K0, K1, sprev, 0.0f);
        }
        #pragma unroll
        for (int j = 0; j < NPRED; j++) {
            float a = P00 + 2.0f * DT * P01 + DT * DT * P11 + q00;
            float c = P01 + DT * P11 + q01;
            float d = P11 + q11;
            P00 = a; P01 = c; P11 = d;
            float s = sqrtf(fmaxf(P00, eps2));
            st[j]   = s;
            dst_[j] = s - sprev;
            sprev = s;
        }
    }
    __syncthreads();

    const int f  = blockIdx.x * BLOCK + tid;
    const int G4 = (B * 5) >> 2;
    if (f >= G4) return;

    const int cb = f % 5;
    const int e  = 4 * (f / 5) + ((cb < 3) ? cb : 3);

    float4 pxm, pym, sm;
    switch (cb) {
        case 0: pxm = make_float4(1,0,0,0); pym = make_float4(0,1,0,0); sm = make_float4(0,0,1,1); break;
        case 1: pxm = make_float4(0,1,0,0); pym = make_float4(0,0,1,0); sm = make_float4(0,0,0,1); break;
        case 2: pxm = make_float4(0,0,1,0); pym = make_float4(0,0,0,1); sm = make_float4(1,0,0,0); break;
        case 3: pxm = make_float4(0,0,0,1); pym = make_float4(0,0,0,0); sm = make_float4(1,1,0,0); break;
        default:pxm = make_float4(0,0,0,0); pym = make_float4(1,0,0,0); sm = make_float4(0,1,1,0); break;
    }

    // ---- prefetch ALL measurement rows (independent loads) ----
    const float2* __restrict__ zin = reinterpret_cast<const float2*>(in);
    float2 zr[NEST + 1];
    #pragma unroll
    for (int t = 0; t <= NEST; t++) zr[t] = zin[(size_t)t * B + e];

    // ---- register-only est recursion ----
    float px = zr[0].x, py = zr[0].y;
    float vx = (zr[1].x - zr[0].x) * (1.0f / DT);
    float vy = (zr[1].y - zr[0].y) * (1.0f / DT);

    float rpx[NEST], rpy[NEST];
    #pragma unroll
    for (int t = 0; t < NEST; t++) {
        px += DT * vx;
        py += DT * vy;
        float4 g = gt[t];
        float yx = zr[t + 1].x - px, yy = zr[t + 1].y - py;
        px += g.x * yx; vx += g.y * yx;
        py += g.x * yy; vy += g.y * yy;
        rpx[t] = px; rpy[t] = py;
    }

    float4* __restrict__ out4 = reinterpret_cast<float4*>(out) + f;
    const long long stride = G4;

    // ---- est rows: full assembly (12 ops) + streaming store ----
    float4 v;  // carries the last est row into the pred phase
    #pragma unroll
    for (int t = 0; t < NEST; t++) {
        const float s = gt[t].z;
        v.x = fmaf(rpx[t], pxm.x, fmaf(rpy[t], pym.x, s * sm.x));
        v.y = fmaf(rpx[t], pxm.y, fmaf(rpy[t], pym.y, s * sm.y));
        v.z = fmaf(rpx[t], pxm.z, fmaf(rpy[t], pym.z, s * sm.z));
        v.w = fmaf(rpx[t], pxm.w, fmaf(rpy[t], pym.w, s * sm.w));
        __stcs(out4 + (long long)t * stride, v);
    }

    // ---- pred rows: incremental assembly (8 ops/row) ----
    // v currently = row NEST-1 (px,py,s_est_last in the masked slots).
    const float dx = DT * vx, dy = DT * vy;
    float4 cvec;
    cvec.x = fmaf(dx, pxm.x, dy * pym.x);
    cvec.y = fmaf(dx, pxm.y, dy * pym.y);
    cvec.z = fmaf(dx, pxm.z, dy * pym.z);
    cvec.w = fmaf(dx, pxm.w, dy * pym.w);

    #pragma unroll
    for (int j = 0; j < NPRED; j++) {
        const float ds = dst_[j];
        v.x = fmaf(ds, sm.x, v.x + cvec.x);
        v.y = fmaf(ds, sm.y, v.y + cvec.y);
        v.z = fmaf(ds, sm.z, v.z + cvec.z);
        v.w = fmaf(ds, sm.w, v.w + cvec.w);
        __stcs(out4 + (long long)(NEST + j) * stride, v);
    }
}

// generic fallback for unexpected shapes
__global__ void kalman_generic(const float* __restrict__ in, float* __restrict__ out,
                               const float* __restrict__ sa_p, const float* __restrict__ so_p,
                               const float* __restrict__ si_p,
                               int B, int n_est, int n_pred) {
    const int b = blockIdx.x * blockDim.x + threadIdx.x;
    if (b >= B) return;
    const float sa = *sa_p, so = *so_p, si = *si_p;
    const float g0  = DT * DT * 0.5f;
    const float q00 = sa * sa * (g0 * g0);
    const float q01 = sa * sa * (g0 * DT);
    const float q11 = sa * sa * (DT * DT);
    const float r   = so * so;
    const float eps2 = EPS_STAT * EPS_STAT;
    float P00 = si * si, P01 = 0.0f, P11 = si * si;
    const float2* zin = reinterpret_cast<const float2*>(in);
    float2 z0 = zin[b], z1 = zin[(size_t)B + b];
    float px = z0.x, py = z0.y;
    float vx = (z1.x - z0.x) / DT, vy = (z1.y - z0.y) / DT;
    for (int t = 0; t < n_est + n_pred; t++) {
        float a = P00 + 2.0f * DT * P01 + DT * DT * P11 + q00;
        float c = P01 + DT * P11 + q01;
        float d = P11 + q11;
        P00 = a; P01 = c; P11 = d;
        px += DT * vx; py += DT * vy;
        if (t < n_est) {
            float2 z = zin[(size_t)(t + 1) * B + b];
            float S = P00 + r, rs = 1.0f / S;
            float K0 = P00 * rs, K1 = P01 * rs;
            float yx = z.x - px, yy = z.y - py;
            px += K0 * yx; vx += K1 * yx;
            py += K0 * yy; vy += K1 * yy;
            float omk = 1.0f - K0;
            float A00 = omk * P00, A01 = omk * P01;
            float A10 = P01 - K1 * P00, A11 = P11 - K1 * P01;
            P00 =  A00 * omk      + r * K0 * K0;
            P01 = -A00 * K1 + A01 + r * K0 * K1;
            P11 = -A10 * K1 + A11 + r * K1 * K1;
        }
        float s = sqrtf(fmaxf(P00, eps2));
        float* dptr = out + (long long)t * B * 5 + (long long)b * 5;
        dptr[0] = px; dptr[1] = py; dptr[2] = s; dptr[3] = s; dptr[4] = 0.0f;
    }
}

extern "C" void kernel_launch(void* const* d_in, const int* in_sizes, int n_in,
                              void* d_out, int out_size) {
    const float* inputs  = (const float*)d_in[0];
    const float* sigma_a = (const float*)d_in[1];
    const float* sigma_o = (const float*)d_in[2];
    const float* sigma_i = (const float*)d_in[3];

    const int T_OBS = 10;
    const int B = in_sizes[0] / (T_OBS * 2);
    const int n_est = T_OBS - 1;                // 9
    const int totalSteps = out_size / (B * 5);  // 39
    const int n_pred = totalSteps - n_est;      // 30

    if (n_est == 9 && n_pred == 30 && (B % 4) == 0) {
        constexpr int BLOCK = 128;
        const int G4 = (B * 5) / 4;
        const int grid = (G4 + BLOCK - 1) / BLOCK;
        kalman_fused<BLOCK, 9, 30><<<grid, BLOCK>>>(
            inputs, (float*)d_out, sigma_a, sigma_o, sigma_i, B);
    } else {
        const int grid = (B + 255) / 256;
        kalman_generic<<<grid, 256>>>(inputs, (float*)d_out,
                                      sigma_a, sigma_o, sigma_i,
                                      B, n_est, n_pred);
    }
}